// round 5
// baseline (speedup 1.0000x reference)
#include <cuda_runtime.h>
#include <cuda_bf16.h>

#define BATCH 16
#define NPTS  1024
#define CDIM  64

// -------- scratch (__device__ globals, allocation-free rule) --------
__device__ float         g_r[BATCH * NPTS * CDIM];      // x@W_root + b_rel (fp32)
__device__ __nv_bfloat16 g_yT_hi[BATCH * CDIM * NPTS];  // (x@W_rel)^T hi, [b][c][j]
__device__ __nv_bfloat16 g_yT_lo[BATCH * CDIM * NPTS];  // lo residual

// ===================== helpers =====================
__device__ __forceinline__ unsigned smem_u32(const void* p) {
    unsigned a;
    asm("{ .reg .u64 t; cvta.to.shared.u64 t, %1; cvt.u32.u64 %0, t; }"
        : "=r"(a) : "l"(p));
    return a;
}
#define CP_ASYNC16(dst, src) \
    asm volatile("cp.async.cg.shared.global [%0], [%1], 16;" :: "r"(dst), "l"(src))
#define CP_COMMIT()  asm volatile("cp.async.commit_group;" ::: "memory")
#define CP_WAITG(n)  asm volatile("cp.async.wait_group %0;" :: "n"(n) : "memory")

__device__ __forceinline__ float2 lds_f2(unsigned a) {
    float2 r;
    asm volatile("ld.shared.v2.f32 {%0,%1}, [%2];" : "=f"(r.x), "=f"(r.y) : "r"(a));
    return r;
}
__device__ __forceinline__ int2 lds_i2(unsigned a) {
    int2 r;
    asm volatile("ld.shared.v2.u32 {%0,%1}, [%2];" : "=r"(r.x), "=r"(r.y) : "r"(a));
    return r;
}
__device__ __forceinline__ void sts_f2(unsigned a, float x, float y) {
    asm volatile("st.shared.v2.f32 [%0], {%1,%2};" :: "r"(a), "f"(x), "f"(y) : "memory");
}
__device__ __forceinline__ void ldx4(unsigned* r, unsigned addr) {
    asm volatile("ldmatrix.sync.aligned.m8n8.x4.shared.b16 {%0,%1,%2,%3}, [%4];"
                 : "=r"(r[0]), "=r"(r[1]), "=r"(r[2]), "=r"(r[3]) : "r"(addr));
}
__device__ __forceinline__ void mma16816(float* d, const unsigned* a,
                                         unsigned b0, unsigned b1) {
    asm volatile("mma.sync.aligned.m16n8k16.row.col.f32.bf16.bf16.f32 "
                 "{%0,%1,%2,%3}, {%4,%5,%6,%7}, {%8,%9}, {%0,%1,%2,%3};"
                 : "+f"(d[0]), "+f"(d[1]), "+f"(d[2]), "+f"(d[3])
                 : "r"(a[0]), "r"(a[1]), "r"(a[2]), "r"(a[3]), "r"(b0), "r"(b1));
}
// 64B-row swizzle for B (8 rows x 64B atom, conflict-free per ldmatrix matrix)
__device__ __forceinline__ unsigned bswz(unsigned off) { return off ^ ((off >> 3) & 0x30); }

__device__ __forceinline__ float wsel(int e, float w0, float w1, float w2, float w3) {
    return e == 0 ? w0 : (e == 1 ? w1 : (e == 2 ? w2 : w3));
}

// ===================== Stage 1 (unchanged, known-good) =====================
__global__ __launch_bounds__(256) void stage1_kernel(
    const float* __restrict__ x, const float* __restrict__ W_rel,
    const float* __restrict__ b_rel, const float* __restrict__ W_root)
{
    __shared__ float xs[64][64];
    __shared__ float wr[64][64];
    __shared__ float wo[64][64];

    const int tid  = threadIdx.x;
    const int row0 = blockIdx.x * 64;

    for (int t = tid; t < 64 * 16; t += 256) {
        const int r = t >> 4, c4 = (t & 15) << 2;
        *(float4*)&wr[r][c4] = *(const float4*)&W_rel[r * 64 + c4];
        *(float4*)&wo[r][c4] = *(const float4*)&W_root[r * 64 + c4];
    }
    for (int t = tid; t < 64 * 16; t += 256) {
        const int r = t >> 4, c4 = (t & 15) << 2;
        float4 v = *(const float4*)&x[(row0 + r) * 64 + c4];
        xs[c4 + 0][r] = v.x; xs[c4 + 1][r] = v.y;
        xs[c4 + 2][r] = v.z; xs[c4 + 3][r] = v.w;
    }
    __syncthreads();

    const int ty = tid >> 4, tx = tid & 15;
    float accY[4][4] = {}, accR[4][4] = {};

#pragma unroll 8
    for (int k = 0; k < 64; k++) {
        const float4 a  = *(const float4*)&xs[k][ty * 4];
        const float4 by = *(const float4*)&wr[k][tx * 4];
        const float4 br = *(const float4*)&wo[k][tx * 4];
        const float av[4]  = {a.x, a.y, a.z, a.w};
        const float byv[4] = {by.x, by.y, by.z, by.w};
        const float brv[4] = {br.x, br.y, br.z, br.w};
#pragma unroll
        for (int r = 0; r < 4; r++)
#pragma unroll
            for (int c = 0; c < 4; c++) {
                accY[r][c] = fmaf(av[r], byv[c], accY[r][c]);
                accR[r][c] = fmaf(av[r], brv[c], accR[r][c]);
            }
    }

    float4 brel = *(const float4*)&b_rel[tx * 4];
    const float brelv[4] = {brel.x, brel.y, brel.z, brel.w};

    const int b  = row0 >> 10;
    const int jg = (row0 & 1023) + ty * 4;

#pragma unroll
    for (int r = 0; r < 4; r++) {
        const int grow = row0 + ty * 4 + r;
        float4 orr;
        orr.x = accR[r][0] + brelv[0]; orr.y = accR[r][1] + brelv[1];
        orr.z = accR[r][2] + brelv[2]; orr.w = accR[r][3] + brelv[3];
        *(float4*)&g_r[grow * 64 + tx * 4] = orr;
    }
#pragma unroll
    for (int c = 0; c < 4; c++) {
        unsigned hp[2], lp[2];
#pragma unroll
        for (int p = 0; p < 2; p++) {
            float v0 = accY[2 * p + 0][c], v1 = accY[2 * p + 1][c];
            __nv_bfloat16 h0 = __float2bfloat16(v0);
            __nv_bfloat16 h1 = __float2bfloat16(v1);
            __nv_bfloat16 l0 = __float2bfloat16(v0 - __bfloat162float(h0));
            __nv_bfloat16 l1 = __float2bfloat16(v1 - __bfloat162float(h1));
            hp[p] = (unsigned)__bfloat16_as_ushort(h0) | ((unsigned)__bfloat16_as_ushort(h1) << 16);
            lp[p] = (unsigned)__bfloat16_as_ushort(l0) | ((unsigned)__bfloat16_as_ushort(l1) << 16);
        }
        const long idx = ((long)(b * 64 + tx * 4 + c) << 10) + jg;
        *(uint2*)&g_yT_hi[idx] = make_uint2(hp[0], hp[1]);
        *(uint2*)&g_yT_lo[idx] = make_uint2(lp[0], lp[1]);
    }
}

// ===================== Stage 2 =====================
// Fully-async pipeline: raw adj/ea + bf16 B via cp.async, 3 stages, j-chunk=32.
// Warps: 4 (M, 16 rows) x 2 (K halves). Convert adj*we[ea]->bf16 hi/lo in regs.
// Stage layout: ADJ [64 x 40w(160B)] @0 (10240), EA @10240 (10240),
//               Bhi @20480 (4096), Blo @24576 (4096). STAGE=28672, 3 stages.
#define STAGE    28672
#define SMEM_DYN (3 * STAGE)
#define NCHUNK   32

__device__ __forceinline__ void issue_chunk(
    unsigned st, int j0, const float* __restrict__ adj_b,
    const int* __restrict__ ea_b,
    const __nv_bfloat16* __restrict__ yhi, const __nv_bfloat16* __restrict__ ylo,
    int i0, int tid)
{
    // adj + ea: 64 rows x 32 f32 (128B/row into 160B stride)
    const int row = tid >> 2;
    const int u0  = (tid * 2) & 7;
    const long gsrc = (long)(i0 + row) * NPTS + j0 + u0 * 4;
    const unsigned da = st + row * 160 + u0 * 16;
    CP_ASYNC16(da,              adj_b + gsrc);
    CP_ASYNC16(da + 16,         adj_b + gsrc + 4);
    CP_ASYNC16(da + 10240,      ea_b + gsrc);
    CP_ASYNC16(da + 10240 + 16, ea_b + gsrc + 4);
    // B: hi/lo 64 rows x 32 bf16 (64B/row, bswz)
    const int tile = tid >> 7;
    const int brow = (tid >> 1) & 63;
    const int cb   = (tid & 1) * 2;
    const __nv_bfloat16* bs = (tile ? ylo : yhi) + ((long)brow << 10) + j0;
    const unsigned bd = st + 20480 + tile * 4096;
    CP_ASYNC16(bd + bswz(brow * 64 + cb * 16),       bs + cb * 8);
    CP_ASYNC16(bd + bswz(brow * 64 + (cb + 1) * 16), bs + (cb + 1) * 8);
    CP_COMMIT();
}

__global__ __launch_bounds__(256, 2) void stage2_kernel(
    const float* __restrict__ adj, const int* __restrict__ ea,
    const float* __restrict__ w_edge, float* __restrict__ out)
{
    extern __shared__ char smem_raw[];
    const unsigned sb = smem_u32(smem_raw);

    const int tid = threadIdx.x, lane = tid & 31, wid = tid >> 5;
    const int wi = wid >> 1, wn = wid & 1;   // M-tile / K-half
    const int b  = blockIdx.x >> 4;
    const int i0 = (blockIdx.x & 15) * 64;

    const float* adj_b = adj + ((long)b << 20);
    const int*   ea_b  = ea  + ((long)b << 20);
    const __nv_bfloat16* yhi = g_yT_hi + ((long)(b * 64) << 10);
    const __nv_bfloat16* ylo = g_yT_lo + ((long)(b * 64) << 10);

    const float w0 = __ldg(w_edge + 0), w1 = __ldg(w_edge + 1),
                w2 = __ldg(w_edge + 2), w3 = __ldg(w_edge + 3);

    // A LDS address (within stage): row = wi*16 + (lane>>2), col = wn*16 + (lane&3)*2
    const unsigned aoff = (unsigned)(wi * 16 + (lane >> 2)) * 160 +
                          (unsigned)(wn * 16 + (lane & 3) * 2) * 4;
    // B ldmatrix address (q=0): matrices = (ntile pair) x (k 8-halves)
    const int l8 = lane & 7, mq = lane >> 3;
    const unsigned boff = bswz((unsigned)(((mq >> 1) * 8 + l8) * 64 + wn * 32 + (mq & 1) * 16));

    float acc[8][4] = {};

    issue_chunk(sb,             0, adj_b, ea_b, yhi, ylo, i0, tid);
    issue_chunk(sb + STAGE,    32, adj_b, ea_b, yhi, ylo, i0, tid);
    issue_chunk(sb + 2 * STAGE, 64, adj_b, ea_b, yhi, ylo, i0, tid);

    unsigned st = sb;
    int snum = 0;
#pragma unroll 1
    for (int t = 0; t < NCHUNK; t++) {
        if (t < NCHUNK - 2)      CP_WAITG(2);
        else if (t == NCHUNK - 2) CP_WAITG(1);
        else                      CP_WAITG(0);
        __syncthreads();

        // ---- A fragments: load raw, apply edge weight, split bf16 hi/lo ----
        unsigned ah[4], al[4];
#pragma unroll
        for (int p = 0; p < 4; p++) {
            // p: 0:(r,k) 1:(r+8,k) 2:(r,k+8) 3:(r+8,k+8)
            const unsigned o = st + aoff + (p & 1) * (8 * 160) + (p >> 1) * 32;
            const float2 av = lds_f2(o);
            const int2   ev = lds_i2(o + 10240);
            const float v0 = av.x * wsel(ev.x, w0, w1, w2, w3);
            const float v1 = av.y * wsel(ev.y, w0, w1, w2, w3);
            const __nv_bfloat16 h0 = __float2bfloat16(v0);
            const __nv_bfloat16 h1 = __float2bfloat16(v1);
            const __nv_bfloat16 g0 = __float2bfloat16(v0 - __bfloat162float(h0));
            const __nv_bfloat16 g1 = __float2bfloat16(v1 - __bfloat162float(h1));
            ah[p] = (unsigned)__bfloat16_as_ushort(h0) | ((unsigned)__bfloat16_as_ushort(h1) << 16);
            al[p] = (unsigned)__bfloat16_as_ushort(g0) | ((unsigned)__bfloat16_as_ushort(g1) << 16);
        }

        // ---- B fragments + MMAs (3-pass split: AhBh + AlBh + AhBl) ----
#pragma unroll
        for (int q = 0; q < 4; q++) {
            unsigned bh[4], bl[4];
            ldx4(bh, st + 20480 + boff + q * 1024);
            ldx4(bl, st + 24576 + boff + q * 1024);
            mma16816(acc[2 * q],     ah, bh[0], bh[1]);
            mma16816(acc[2 * q],     al, bh[0], bh[1]);
            mma16816(acc[2 * q],     ah, bl[0], bl[1]);
            mma16816(acc[2 * q + 1], ah, bh[2], bh[3]);
            mma16816(acc[2 * q + 1], al, bh[2], bh[3]);
            mma16816(acc[2 * q + 1], ah, bl[2], bl[3]);
        }
        __syncthreads();
        if (t + 3 < NCHUNK)
            issue_chunk(st, (t + 3) * 32, adj_b, ea_b, yhi, ylo, i0, tid);
        snum = (snum == 2) ? 0 : snum + 1;
        st = sb + (unsigned)snum * STAGE;
    }

    // ---- K-half reduction through smem (red[64][66] f32 at sb) ----
    const int gid = lane >> 2, tig = lane & 3;
    if (wn == 1) {
#pragma unroll
        for (int nt = 0; nt < 8; nt++) {
            const unsigned c4 = (unsigned)(nt * 8 + tig * 2) * 4;
            sts_f2(sb + (unsigned)(wi * 16 + gid) * 264 + c4,     acc[nt][0], acc[nt][1]);
            sts_f2(sb + (unsigned)(wi * 16 + gid + 8) * 264 + c4, acc[nt][2], acc[nt][3]);
        }
    }
    __syncthreads();
    if (wn == 0) {
        const int grow = b * NPTS + i0 + wi * 16 + gid;
#pragma unroll
        for (int nt = 0; nt < 8; nt++) {
            const int  col  = nt * 8 + tig * 2;
            const unsigned c4 = (unsigned)col * 4;
            const float2 p0 = lds_f2(sb + (unsigned)(wi * 16 + gid) * 264 + c4);
            const float2 p1 = lds_f2(sb + (unsigned)(wi * 16 + gid + 8) * 264 + c4);
            const long idx0 = (long)grow * 64 + col;
            const long idx1 = (long)(grow + 8) * 64 + col;
            const float2 r0 = *(const float2*)&g_r[idx0];
            const float2 r1 = *(const float2*)&g_r[idx1];
            float2 o0, o1;
            o0.x = acc[nt][0] + p0.x + r0.x; o0.y = acc[nt][1] + p0.y + r0.y;
            o1.x = acc[nt][2] + p1.x + r1.x; o1.y = acc[nt][3] + p1.y + r1.y;
            *(float2*)&out[idx0] = o0;
            *(float2*)&out[idx1] = o1;
        }
    }
}

// ===================== launch =====================
extern "C" void kernel_launch(void* const* d_in, const int* in_sizes, int n_in,
                              void* d_out, int out_size)
{
    const float* x      = (const float*)d_in[0];
    const float* adj    = (const float*)d_in[1];
    const int*   ea     = (const int*)d_in[2];
    const float* W_rel  = (const float*)d_in[3];
    const float* b_rel  = (const float*)d_in[4];
    const float* W_root = (const float*)d_in[5];
    const float* w_edge = (const float*)d_in[6];
    float* out = (float*)d_out;

    static bool attr_set = false;
    if (!attr_set) {
        cudaFuncSetAttribute(stage2_kernel,
                             cudaFuncAttributeMaxDynamicSharedMemorySize, SMEM_DYN);
        attr_set = true;
    }

    stage1_kernel<<<(BATCH * NPTS) / 64, 256>>>(x, W_rel, b_rel, W_root);
    stage2_kernel<<<BATCH * (NPTS / 64), 256, SMEM_DYN>>>(adj, ea, w_edge, out);
}

// round 6
// speedup vs baseline: 1.5159x; 1.5159x over previous
#include <cuda_runtime.h>
#include <cuda_bf16.h>

#define BATCH 16
#define NPTS  1024
#define CDIM  64

// -------- scratch (__device__ globals, allocation-free rule) --------
__device__ float         g_r[BATCH * NPTS * CDIM];      // x@W_root + b_rel (fp32)
__device__ __nv_bfloat16 g_yT_hi[BATCH * CDIM * NPTS];  // (x@W_rel)^T hi, [b][c][j]
__device__ __nv_bfloat16 g_yT_lo[BATCH * CDIM * NPTS];  // lo residual

// ===================== helpers =====================
__device__ __forceinline__ unsigned smem_u32(const void* p) {
    unsigned a;
    asm("{ .reg .u64 t; cvta.to.shared.u64 t, %1; cvt.u32.u64 %0, t; }"
        : "=r"(a) : "l"(p));
    return a;
}
#define CP_ASYNC16(dst, src) \
    asm volatile("cp.async.cg.shared.global [%0], [%1], 16;" :: "r"(dst), "l"(src))
#define CP_COMMIT()  asm volatile("cp.async.commit_group;" ::: "memory")
#define STS128(addr, r0, r1, r2, r3) \
    asm volatile("st.shared.v4.b32 [%0], {%1,%2,%3,%4};" \
                 :: "r"(addr), "r"(r0), "r"(r1), "r"(r2), "r"(r3) : "memory")

__device__ __forceinline__ unsigned swz(unsigned off) { return off ^ ((off >> 3) & 0x70); }

__device__ __forceinline__ void ldx4(unsigned* r, unsigned addr) {
    asm volatile("ldmatrix.sync.aligned.m8n8.x4.shared.b16 {%0,%1,%2,%3}, [%4];"
                 : "=r"(r[0]), "=r"(r[1]), "=r"(r[2]), "=r"(r[3]) : "r"(addr));
}
__device__ __forceinline__ void mma16816(float* d, const unsigned* a,
                                         unsigned b0, unsigned b1) {
    asm volatile("mma.sync.aligned.m16n8k16.row.col.f32.bf16.bf16.f32 "
                 "{%0,%1,%2,%3}, {%4,%5,%6,%7}, {%8,%9}, {%0,%1,%2,%3};"
                 : "+f"(d[0]), "+f"(d[1]), "+f"(d[2]), "+f"(d[3])
                 : "r"(a[0]), "r"(a[1]), "r"(a[2]), "r"(a[3]), "r"(b0), "r"(b1));
}
__device__ __forceinline__ float wsel(int e, float w0, float w1, float w2, float w3) {
    return e == 0 ? w0 : (e == 1 ? w1 : (e == 2 ? w2 : w3));
}

// ===================== Stage 1 (unchanged, known-good) =====================
__global__ __launch_bounds__(256) void stage1_kernel(
    const float* __restrict__ x, const float* __restrict__ W_rel,
    const float* __restrict__ b_rel, const float* __restrict__ W_root)
{
    __shared__ float xs[64][64];
    __shared__ float wr[64][64];
    __shared__ float wo[64][64];

    const int tid  = threadIdx.x;
    const int row0 = blockIdx.x * 64;

    for (int t = tid; t < 64 * 16; t += 256) {
        const int r = t >> 4, c4 = (t & 15) << 2;
        *(float4*)&wr[r][c4] = *(const float4*)&W_rel[r * 64 + c4];
        *(float4*)&wo[r][c4] = *(const float4*)&W_root[r * 64 + c4];
    }
    for (int t = tid; t < 64 * 16; t += 256) {
        const int r = t >> 4, c4 = (t & 15) << 2;
        float4 v = *(const float4*)&x[(row0 + r) * 64 + c4];
        xs[c4 + 0][r] = v.x; xs[c4 + 1][r] = v.y;
        xs[c4 + 2][r] = v.z; xs[c4 + 3][r] = v.w;
    }
    __syncthreads();

    const int ty = tid >> 4, tx = tid & 15;
    float accY[4][4] = {}, accR[4][4] = {};

#pragma unroll 8
    for (int k = 0; k < 64; k++) {
        const float4 a  = *(const float4*)&xs[k][ty * 4];
        const float4 by = *(const float4*)&wr[k][tx * 4];
        const float4 br = *(const float4*)&wo[k][tx * 4];
        const float av[4]  = {a.x, a.y, a.z, a.w};
        const float byv[4] = {by.x, by.y, by.z, by.w};
        const float brv[4] = {br.x, br.y, br.z, br.w};
#pragma unroll
        for (int r = 0; r < 4; r++)
#pragma unroll
            for (int c = 0; c < 4; c++) {
                accY[r][c] = fmaf(av[r], byv[c], accY[r][c]);
                accR[r][c] = fmaf(av[r], brv[c], accR[r][c]);
            }
    }

    float4 brel = *(const float4*)&b_rel[tx * 4];
    const float brelv[4] = {brel.x, brel.y, brel.z, brel.w};

    const int b  = row0 >> 10;
    const int jg = (row0 & 1023) + ty * 4;

#pragma unroll
    for (int r = 0; r < 4; r++) {
        const int grow = row0 + ty * 4 + r;
        float4 orr;
        orr.x = accR[r][0] + brelv[0]; orr.y = accR[r][1] + brelv[1];
        orr.z = accR[r][2] + brelv[2]; orr.w = accR[r][3] + brelv[3];
        *(float4*)&g_r[grow * 64 + tx * 4] = orr;
    }
#pragma unroll
    for (int c = 0; c < 4; c++) {
        unsigned hp[2], lp[2];
#pragma unroll
        for (int p = 0; p < 2; p++) {
            float v0 = accY[2 * p + 0][c], v1 = accY[2 * p + 1][c];
            __nv_bfloat16 h0 = __float2bfloat16(v0);
            __nv_bfloat16 h1 = __float2bfloat16(v1);
            __nv_bfloat16 l0 = __float2bfloat16(v0 - __bfloat162float(h0));
            __nv_bfloat16 l1 = __float2bfloat16(v1 - __bfloat162float(h1));
            hp[p] = (unsigned)__bfloat16_as_ushort(h0) | ((unsigned)__bfloat16_as_ushort(h1) << 16);
            lp[p] = (unsigned)__bfloat16_as_ushort(l0) | ((unsigned)__bfloat16_as_ushort(l1) << 16);
        }
        const long idx = ((long)(b * 64 + tx * 4 + c) << 10) + jg;
        *(uint2*)&g_yT_hi[idx] = make_uint2(hp[0], hp[1]);
        *(uint2*)&g_yT_lo[idx] = make_uint2(lp[0], lp[1]);
    }
}

// ===================== Stage 2 =====================
// out[b, i0:i0+32, :] = (adj*we[ea]) @ y + r
// 512 CTAs (16 b x 32 i-tiles of 32 rows), 256 threads, 3 CTAs/SM.
// A: LDG->reg convert->STS bf16 hi/lo, 2 stages x 8KB.
// B: cp.async bf16 hi/lo from g_yT, 3 stages x 16KB. j-chunk 64, 16 chunks.
#define NCHUNK  16
#define A_ST(t)  (((t) & 1) * 8192)            // hi +0, lo +4096
#define B_ST(t)  (16384 + ((t) % 3) * 16384)   // hi +0, lo +8192
#define SMEM_DYN 65536

__device__ __forceinline__ void issue_B(unsigned sbp, int j0,
                                        const __nv_bfloat16* __restrict__ yhi,
                                        const __nv_bfloat16* __restrict__ ylo,
                                        int tid) {
#pragma unroll
    for (int v = 0; v < 4; v++) {
        const int idx  = tid + v * 256;     // 0..1023 16B slots
        const int tile = idx >> 9;          // 0 hi, 1 lo
        const int row  = (idx >> 3) & 63;   // n (output channel)
        const int cb   = idx & 7;
        const __nv_bfloat16* src =
            (tile ? ylo : yhi) + ((long)row << 10) + j0 + cb * 8;
        CP_ASYNC16(sbp + tile * 8192 + swz(row * 128 + cb * 16), src);
    }
    CP_COMMIT();
}

__global__ __launch_bounds__(256, 3) void stage2_kernel(
    const float* __restrict__ adj, const int* __restrict__ ea,
    const float* __restrict__ w_edge, float* __restrict__ out)
{
    extern __shared__ char smem_raw[];
    const unsigned sb = smem_u32(smem_raw);

    const int tid = threadIdx.x, lane = tid & 31, wid = tid >> 5;
    const int wi = wid & 1, wn = wid >> 1;       // M half (16) x N quarter (16)
    const int b  = blockIdx.x >> 5;
    const int i0 = (blockIdx.x & 31) * 32;

    const float* adj_b = adj + ((long)b << 20);
    const int*   ea_b  = ea  + ((long)b << 20);
    const __nv_bfloat16* yhi = g_yT_hi + ((long)(b * 64) << 10);
    const __nv_bfloat16* ylo = g_yT_lo + ((long)(b * 64) << 10);

    const float w0 = __ldg(w_edge + 0), w1 = __ldg(w_edge + 1),
                w2 = __ldg(w_edge + 2), w3 = __ldg(w_edge + 3);

    // A producer: each thread owns (row = tid>>3) x 8 cols at c0 = (tid&7)*8
    const int  arow = tid >> 3;
    const int  ac0  = (tid & 7) << 3;
    const long rowbase = (long)(i0 + arow) * NPTS + ac0;

    // ldmatrix lane addressing
    const int l8 = lane & 7, mm = lane >> 3;
    const unsigned aRowOff = (unsigned)(wi * 16 + (mm & 1) * 8 + l8) * 128;
    const unsigned aColX   = ((unsigned)(mm >> 1) * 16) ^ ((unsigned)l8 << 4);
    const unsigned bRowOff = (unsigned)(wn * 16 + l8) * 128;
    const unsigned bColX   = ((unsigned)mm * 16) ^ ((unsigned)l8 << 4);

    float acc[2][4] = {};
    float4 pa[2]; int4 pe[2];

    // prologue: B for chunks 0,1 in flight; A chunk 0 in regs
    issue_B(sb + B_ST(0), 0,  yhi, ylo, tid);
    issue_B(sb + B_ST(1), 64, yhi, ylo, tid);
#pragma unroll
    for (int q = 0; q < 2; q++) {
        pa[q] = __ldg((const float4*)(adj_b + rowbase + q * 4));
        pe[q] = __ldg((const int4*)(ea_b + rowbase + q * 4));
    }

#pragma unroll 1
    for (int t = 0; t < NCHUNK; t++) {
        // ---- convert A(t) from regs -> smem stage (bf16 hi/lo) ----
        {
            unsigned hp[4], lp[4];
#pragma unroll
            for (int q = 0; q < 2; q++) {
                const float av[4] = {pa[q].x, pa[q].y, pa[q].z, pa[q].w};
                const int   ev[4] = {pe[q].x, pe[q].y, pe[q].z, pe[q].w};
#pragma unroll
                for (int p = 0; p < 2; p++) {
                    float v0 = av[2 * p + 0] * wsel(ev[2 * p + 0], w0, w1, w2, w3);
                    float v1 = av[2 * p + 1] * wsel(ev[2 * p + 1], w0, w1, w2, w3);
                    __nv_bfloat16 h0 = __float2bfloat16(v0);
                    __nv_bfloat16 h1 = __float2bfloat16(v1);
                    __nv_bfloat16 g0 = __float2bfloat16(v0 - __bfloat162float(h0));
                    __nv_bfloat16 g1 = __float2bfloat16(v1 - __bfloat162float(h1));
                    hp[q * 2 + p] = (unsigned)__bfloat16_as_ushort(h0) |
                                    ((unsigned)__bfloat16_as_ushort(h1) << 16);
                    lp[q * 2 + p] = (unsigned)__bfloat16_as_ushort(g0) |
                                    ((unsigned)__bfloat16_as_ushort(g1) << 16);
                }
            }
            const unsigned ao = sb + A_ST(t) + swz((unsigned)arow * 128 + ac0 * 2);
            STS128(ao,        hp[0], hp[1], hp[2], hp[3]);
            STS128(ao + 4096, lp[0], lp[1], lp[2], lp[3]);
        }
        // ---- prefetch A(t+1) ----
        if (t + 1 < NCHUNK) {
            const long src = rowbase + (t + 1) * 64;
#pragma unroll
            for (int q = 0; q < 2; q++) {
                pa[q] = __ldg((const float4*)(adj_b + src + q * 4));
                pe[q] = __ldg((const int4*)(ea_b + src + q * 4));
            }
        }
        // ---- B(t) complete for all threads ----
        if (t < NCHUNK - 1) asm volatile("cp.async.wait_group 1;" ::: "memory");
        else                asm volatile("cp.async.wait_group 0;" ::: "memory");
        __syncthreads();
        // ---- refill B ring (slot readers finished before the sync above) ----
        if (t + 2 < NCHUNK)
            issue_B(sb + B_ST(t + 2), (t + 2) * 64, yhi, ylo, tid);
        // ---- compute chunk t ----
        {
            const unsigned aHi = sb + A_ST(t), aLo = aHi + 4096;
            const unsigned bHi = sb + B_ST(t), bLo = bHi + 8192;
#pragma unroll
            for (int kh = 0; kh < 2; kh++) {
                unsigned ah0[4], ah1[4], al0[4], al1[4];
                ldx4(ah0, aHi + aRowOff + (((2 * kh + 0) * 32) ^ aColX));
                ldx4(ah1, aHi + aRowOff + (((2 * kh + 1) * 32) ^ aColX));
                ldx4(al0, aLo + aRowOff + (((2 * kh + 0) * 32) ^ aColX));
                ldx4(al1, aLo + aRowOff + (((2 * kh + 1) * 32) ^ aColX));
#pragma unroll
                for (int nt = 0; nt < 2; nt++) {
                    unsigned bh[4], bl[4];
                    ldx4(bh, bHi + bRowOff + nt * 1024 + ((kh * 64) ^ bColX));
                    ldx4(bl, bLo + bRowOff + nt * 1024 + ((kh * 64) ^ bColX));
                    mma16816(acc[nt], ah0, bh[0], bh[1]);
                    mma16816(acc[nt], ah1, bh[2], bh[3]);
                    mma16816(acc[nt], al0, bh[0], bh[1]);
                    mma16816(acc[nt], al1, bh[2], bh[3]);
                    mma16816(acc[nt], ah0, bl[0], bl[1]);
                    mma16816(acc[nt], ah1, bl[2], bl[3]);
                }
            }
        }
    }

    // ---- epilogue: add r, store ----
    const int gid = lane >> 2, tig = lane & 3;
    const int grow = b * NPTS + i0 + wi * 16 + gid;
#pragma unroll
    for (int nt = 0; nt < 2; nt++) {
        const int  col  = wn * 16 + nt * 8 + tig * 2;
        const long idx0 = (long)grow * 64 + col;
        const long idx1 = (long)(grow + 8) * 64 + col;
        const float2 r0 = *(const float2*)&g_r[idx0];
        const float2 r1 = *(const float2*)&g_r[idx1];
        float2 o0, o1;
        o0.x = acc[nt][0] + r0.x; o0.y = acc[nt][1] + r0.y;
        o1.x = acc[nt][2] + r1.x; o1.y = acc[nt][3] + r1.y;
        *(float2*)&out[idx0] = o0;
        *(float2*)&out[idx1] = o1;
    }
}

// ===================== launch =====================
extern "C" void kernel_launch(void* const* d_in, const int* in_sizes, int n_in,
                              void* d_out, int out_size)
{
    const float* x      = (const float*)d_in[0];
    const float* adj    = (const float*)d_in[1];
    const int*   ea     = (const int*)d_in[2];
    const float* W_rel  = (const float*)d_in[3];
    const float* b_rel  = (const float*)d_in[4];
    const float* W_root = (const float*)d_in[5];
    const float* w_edge = (const float*)d_in[6];
    float* out = (float*)d_out;

    static bool attr_set = false;
    if (!attr_set) {
        cudaFuncSetAttribute(stage2_kernel,
                             cudaFuncAttributeMaxDynamicSharedMemorySize, SMEM_DYN);
        attr_set = true;
    }

    stage1_kernel<<<(BATCH * NPTS) / 64, 256>>>(x, W_rel, b_rel, W_root);
    stage2_kernel<<<BATCH * 32, 256, SMEM_DYN>>>(adj, ea, w_edge, out);
}

// round 7
// speedup vs baseline: 1.8197x; 1.2004x over previous
#include <cuda_runtime.h>
#include <cuda_bf16.h>

#define BATCH 16
#define NPTS  1024
#define CDIM  64

// -------- scratch (__device__ globals, allocation-free rule) --------
__device__ float         g_r[BATCH * NPTS * CDIM];      // x@W_root + b_rel (fp32)
__device__ __nv_bfloat16 g_yT_hi[BATCH * CDIM * NPTS];  // (x@W_rel)^T hi, [b][c][j]
__device__ __nv_bfloat16 g_yT_lo[BATCH * CDIM * NPTS];  // lo residual

// ===================== helpers =====================
__device__ __forceinline__ unsigned smem_u32(const void* p) {
    unsigned a;
    asm("{ .reg .u64 t; cvta.to.shared.u64 t, %1; cvt.u32.u64 %0, t; }"
        : "=r"(a) : "l"(p));
    return a;
}
#define CP_ASYNC16(dst, src) \
    asm volatile("cp.async.cg.shared.global [%0], [%1], 16;" :: "r"(dst), "l"(src))
#define CP_COMMIT()  asm volatile("cp.async.commit_group;" ::: "memory")
#define STS128(addr, r0, r1, r2, r3) \
    asm volatile("st.shared.v4.b32 [%0], {%1,%2,%3,%4};" \
                 :: "r"(addr), "r"(r0), "r"(r1), "r"(r2), "r"(r3) : "memory")

__device__ __forceinline__ unsigned swz(unsigned off) { return off ^ ((off >> 3) & 0x70); }

__device__ __forceinline__ void ldx4(unsigned* r, unsigned addr) {
    asm volatile("ldmatrix.sync.aligned.m8n8.x4.shared.b16 {%0,%1,%2,%3}, [%4];"
                 : "=r"(r[0]), "=r"(r[1]), "=r"(r[2]), "=r"(r[3]) : "r"(addr));
}
__device__ __forceinline__ void mma16816(float* d, const unsigned* a,
                                         unsigned b0, unsigned b1) {
    asm volatile("mma.sync.aligned.m16n8k16.row.col.f32.bf16.bf16.f32 "
                 "{%0,%1,%2,%3}, {%4,%5,%6,%7}, {%8,%9}, {%0,%1,%2,%3};"
                 : "+f"(d[0]), "+f"(d[1]), "+f"(d[2]), "+f"(d[3])
                 : "r"(a[0]), "r"(a[1]), "r"(a[2]), "r"(a[3]), "r"(b0), "r"(b1));
}
__device__ __forceinline__ float wsel(int e, float w0, float w1, float w2, float w3) {
    return e == 0 ? w0 : (e == 1 ? w1 : (e == 2 ? w2 : w3));
}

// ===================== Stage 1 (unchanged, known-good) =====================
__global__ __launch_bounds__(256) void stage1_kernel(
    const float* __restrict__ x, const float* __restrict__ W_rel,
    const float* __restrict__ b_rel, const float* __restrict__ W_root)
{
    __shared__ float xs[64][64];
    __shared__ float wr[64][64];
    __shared__ float wo[64][64];

    const int tid  = threadIdx.x;
    const int row0 = blockIdx.x * 64;

    for (int t = tid; t < 64 * 16; t += 256) {
        const int r = t >> 4, c4 = (t & 15) << 2;
        *(float4*)&wr[r][c4] = *(const float4*)&W_rel[r * 64 + c4];
        *(float4*)&wo[r][c4] = *(const float4*)&W_root[r * 64 + c4];
    }
    for (int t = tid; t < 64 * 16; t += 256) {
        const int r = t >> 4, c4 = (t & 15) << 2;
        float4 v = *(const float4*)&x[(row0 + r) * 64 + c4];
        xs[c4 + 0][r] = v.x; xs[c4 + 1][r] = v.y;
        xs[c4 + 2][r] = v.z; xs[c4 + 3][r] = v.w;
    }
    __syncthreads();

    const int ty = tid >> 4, tx = tid & 15;
    float accY[4][4] = {}, accR[4][4] = {};

#pragma unroll 8
    for (int k = 0; k < 64; k++) {
        const float4 a  = *(const float4*)&xs[k][ty * 4];
        const float4 by = *(const float4*)&wr[k][tx * 4];
        const float4 br = *(const float4*)&wo[k][tx * 4];
        const float av[4]  = {a.x, a.y, a.z, a.w};
        const float byv[4] = {by.x, by.y, by.z, by.w};
        const float brv[4] = {br.x, br.y, br.z, br.w};
#pragma unroll
        for (int r = 0; r < 4; r++)
#pragma unroll
            for (int c = 0; c < 4; c++) {
                accY[r][c] = fmaf(av[r], byv[c], accY[r][c]);
                accR[r][c] = fmaf(av[r], brv[c], accR[r][c]);
            }
    }

    float4 brel = *(const float4*)&b_rel[tx * 4];
    const float brelv[4] = {brel.x, brel.y, brel.z, brel.w};

    const int b  = row0 >> 10;
    const int jg = (row0 & 1023) + ty * 4;

#pragma unroll
    for (int r = 0; r < 4; r++) {
        const int grow = row0 + ty * 4 + r;
        float4 orr;
        orr.x = accR[r][0] + brelv[0]; orr.y = accR[r][1] + brelv[1];
        orr.z = accR[r][2] + brelv[2]; orr.w = accR[r][3] + brelv[3];
        *(float4*)&g_r[grow * 64 + tx * 4] = orr;
    }
#pragma unroll
    for (int c = 0; c < 4; c++) {
        unsigned hp[2], lp[2];
#pragma unroll
        for (int p = 0; p < 2; p++) {
            float v0 = accY[2 * p + 0][c], v1 = accY[2 * p + 1][c];
            __nv_bfloat16 h0 = __float2bfloat16(v0);
            __nv_bfloat16 h1 = __float2bfloat16(v1);
            __nv_bfloat16 l0 = __float2bfloat16(v0 - __bfloat162float(h0));
            __nv_bfloat16 l1 = __float2bfloat16(v1 - __bfloat162float(h1));
            hp[p] = (unsigned)__bfloat16_as_ushort(h0) | ((unsigned)__bfloat16_as_ushort(h1) << 16);
            lp[p] = (unsigned)__bfloat16_as_ushort(l0) | ((unsigned)__bfloat16_as_ushort(l1) << 16);
        }
        const long idx = ((long)(b * 64 + tx * 4 + c) << 10) + jg;
        *(uint2*)&g_yT_hi[idx] = make_uint2(hp[0], hp[1]);
        *(uint2*)&g_yT_lo[idx] = make_uint2(lp[0], lp[1]);
    }
}

// ===================== Stage 2 =====================
// out[b, i0:i0+64, :] = (adj*we[ea]) @ y + r
// 256 CTAs (16 b x 16 i-tiles of 64 rows), 512 threads, 2 CTAs/SM (<=64 regs).
// Warp grid 4(M:16) x 4(N:16). A: LDG->reg convert->STS bf16 hi/lo, 2 stages.
// B: cp.async bf16 hi/lo, 3 stages. j-chunk 64, 16 chunks.
#define NCHUNK  16
#define A_ST(t)  (((t) & 1) * 16384)           // hi +0, lo +8192
#define B_ST(t)  (32768 + ((t) % 3) * 16384)   // hi +0, lo +8192
#define SMEM_DYN 81920

__device__ __forceinline__ void issue_B(unsigned sbp, int j0,
                                        const __nv_bfloat16* __restrict__ yhi,
                                        const __nv_bfloat16* __restrict__ ylo,
                                        int tid) {
#pragma unroll
    for (int v = 0; v < 2; v++) {
        const int idx  = tid + v * 512;     // 0..1023 16B slots
        const int tile = idx >> 9;          // 0 hi, 1 lo
        const int row  = (idx >> 3) & 63;   // n (output channel)
        const int cb   = idx & 7;
        const __nv_bfloat16* src =
            (tile ? ylo : yhi) + ((long)row << 10) + j0 + cb * 8;
        CP_ASYNC16(sbp + tile * 8192 + swz(row * 128 + cb * 16), src);
    }
    CP_COMMIT();
}

__global__ __launch_bounds__(512, 2) void stage2_kernel(
    const float* __restrict__ adj, const int* __restrict__ ea,
    const float* __restrict__ w_edge, float* __restrict__ out)
{
    extern __shared__ char smem_raw[];
    const unsigned sb = smem_u32(smem_raw);

    const int tid = threadIdx.x, lane = tid & 31, wid = tid >> 5;
    const int wi = wid & 3, wn = wid >> 2;       // M quarter (16) x N quarter (16)
    const int b  = blockIdx.x >> 4;
    const int i0 = (blockIdx.x & 15) * 64;

    const float* adj_b = adj + ((long)b << 20);
    const int*   ea_b  = ea  + ((long)b << 20);
    const __nv_bfloat16* yhi = g_yT_hi + ((long)(b * 64) << 10);
    const __nv_bfloat16* ylo = g_yT_lo + ((long)(b * 64) << 10);

    const float w0 = __ldg(w_edge + 0), w1 = __ldg(w_edge + 1),
                w2 = __ldg(w_edge + 2), w3 = __ldg(w_edge + 3);

    // A producer: each thread owns (row = tid>>3) x 8 cols at c0 = (tid&7)*8
    const int  arow = tid >> 3;              // 0..63
    const int  ac0  = (tid & 7) << 3;
    const long rowbase = (long)(i0 + arow) * NPTS + ac0;

    // ldmatrix lane addressing
    const int l8 = lane & 7, mm = lane >> 3;
    const unsigned aRowOff = (unsigned)(wi * 16 + (mm & 1) * 8 + l8) * 128;
    const unsigned aColX   = ((unsigned)(mm >> 1) * 16) ^ ((unsigned)l8 << 4);
    const unsigned bRowOff = (unsigned)(wn * 16 + l8) * 128;
    const unsigned bColX   = ((unsigned)mm * 16) ^ ((unsigned)l8 << 4);

    float acc[2][4] = {};
    float4 pa[2]; int4 pe[2];

    // prologue: B for chunks 0,1 in flight; A chunk 0 in regs
    issue_B(sb + B_ST(0), 0,  yhi, ylo, tid);
    issue_B(sb + B_ST(1), 64, yhi, ylo, tid);
#pragma unroll
    for (int q = 0; q < 2; q++) {
        pa[q] = __ldg((const float4*)(adj_b + rowbase + q * 4));
        pe[q] = __ldg((const int4*)(ea_b + rowbase + q * 4));
    }

#pragma unroll 1
    for (int t = 0; t < NCHUNK; t++) {
        // ---- convert A(t) from regs -> smem stage (bf16 hi/lo) ----
        {
            unsigned hp[4], lp[4];
#pragma unroll
            for (int q = 0; q < 2; q++) {
                const float av[4] = {pa[q].x, pa[q].y, pa[q].z, pa[q].w};
                const int   ev[4] = {pe[q].x, pe[q].y, pe[q].z, pe[q].w};
#pragma unroll
                for (int p = 0; p < 2; p++) {
                    float v0 = av[2 * p + 0] * wsel(ev[2 * p + 0], w0, w1, w2, w3);
                    float v1 = av[2 * p + 1] * wsel(ev[2 * p + 1], w0, w1, w2, w3);
                    __nv_bfloat16 h0 = __float2bfloat16(v0);
                    __nv_bfloat16 h1 = __float2bfloat16(v1);
                    __nv_bfloat16 g0 = __float2bfloat16(v0 - __bfloat162float(h0));
                    __nv_bfloat16 g1 = __float2bfloat16(v1 - __bfloat162float(h1));
                    hp[q * 2 + p] = (unsigned)__bfloat16_as_ushort(h0) |
                                    ((unsigned)__bfloat16_as_ushort(h1) << 16);
                    lp[q * 2 + p] = (unsigned)__bfloat16_as_ushort(g0) |
                                    ((unsigned)__bfloat16_as_ushort(g1) << 16);
                }
            }
            const unsigned ao = sb + A_ST(t) + swz((unsigned)arow * 128 + ac0 * 2);
            STS128(ao,        hp[0], hp[1], hp[2], hp[3]);
            STS128(ao + 8192, lp[0], lp[1], lp[2], lp[3]);
        }
        // ---- prefetch A(t+1) ----
        if (t + 1 < NCHUNK) {
            const long src = rowbase + (t + 1) * 64;
#pragma unroll
            for (int q = 0; q < 2; q++) {
                pa[q] = __ldg((const float4*)(adj_b + src + q * 4));
                pe[q] = __ldg((const int4*)(ea_b + src + q * 4));
            }
        }
        // ---- B(t) complete for all threads ----
        if (t < NCHUNK - 1) asm volatile("cp.async.wait_group 1;" ::: "memory");
        else                asm volatile("cp.async.wait_group 0;" ::: "memory");
        __syncthreads();
        // ---- refill B ring (slot readers finished before the sync above) ----
        if (t + 2 < NCHUNK)
            issue_B(sb + B_ST(t + 2), (t + 2) * 64, yhi, ylo, tid);
        // ---- compute chunk t ----
        {
            const unsigned aHi = sb + A_ST(t), aLo = aHi + 8192;
            const unsigned bHi = sb + B_ST(t), bLo = bHi + 8192;
#pragma unroll
            for (int kh = 0; kh < 2; kh++) {
                unsigned ah0[4], ah1[4], al0[4], al1[4];
                ldx4(ah0, aHi + aRowOff + (((2 * kh + 0) * 32) ^ aColX));
                ldx4(ah1, aHi + aRowOff + (((2 * kh + 1) * 32) ^ aColX));
                ldx4(al0, aLo + aRowOff + (((2 * kh + 0) * 32) ^ aColX));
                ldx4(al1, aLo + aRowOff + (((2 * kh + 1) * 32) ^ aColX));
#pragma unroll
                for (int nt = 0; nt < 2; nt++) {
                    unsigned bh[4], bl[4];
                    ldx4(bh, bHi + bRowOff + nt * 1024 + ((kh * 64) ^ bColX));
                    ldx4(bl, bLo + bRowOff + nt * 1024 + ((kh * 64) ^ bColX));
                    mma16816(acc[nt], ah0, bh[0], bh[1]);
                    mma16816(acc[nt], ah1, bh[2], bh[3]);
                    mma16816(acc[nt], al0, bh[0], bh[1]);
                    mma16816(acc[nt], al1, bh[2], bh[3]);
                    mma16816(acc[nt], ah0, bl[0], bl[1]);
                    mma16816(acc[nt], ah1, bl[2], bl[3]);
                }
            }
        }
    }

    // ---- epilogue: add r, store ----
    const int gid = lane >> 2, tig = lane & 3;
    const int grow = b * NPTS + i0 + wi * 16 + gid;
#pragma unroll
    for (int nt = 0; nt < 2; nt++) {
        const int  col  = wn * 16 + nt * 8 + tig * 2;
        const long idx0 = (long)grow * 64 + col;
        const long idx1 = (long)(grow + 8) * 64 + col;
        const float2 r0 = *(const float2*)&g_r[idx0];
        const float2 r1 = *(const float2*)&g_r[idx1];
        float2 o0, o1;
        o0.x = acc[nt][0] + r0.x; o0.y = acc[nt][1] + r0.y;
        o1.x = acc[nt][2] + r1.x; o1.y = acc[nt][3] + r1.y;
        *(float2*)&out[idx0] = o0;
        *(float2*)&out[idx1] = o1;
    }
}

// ===================== launch =====================
extern "C" void kernel_launch(void* const* d_in, const int* in_sizes, int n_in,
                              void* d_out, int out_size)
{
    const float* x      = (const float*)d_in[0];
    const float* adj    = (const float*)d_in[1];
    const int*   ea     = (const int*)d_in[2];
    const float* W_rel  = (const float*)d_in[3];
    const float* b_rel  = (const float*)d_in[4];
    const float* W_root = (const float*)d_in[5];
    const float* w_edge = (const float*)d_in[6];
    float* out = (float*)d_out;

    static bool attr_set = false;
    if (!attr_set) {
        cudaFuncSetAttribute(stage2_kernel,
                             cudaFuncAttributeMaxDynamicSharedMemorySize, SMEM_DYN);
        attr_set = true;
    }

    stage1_kernel<<<(BATCH * NPTS) / 64, 256>>>(x, W_rel, b_rel, W_root);
    stage2_kernel<<<BATCH * 16, 512, SMEM_DYN>>>(adj, ea, w_edge, out);
}